// round 2
// baseline (speedup 1.0000x reference)
#include <cuda_runtime.h>
#include <math.h>

// ---------------- problem constants ----------------
#define NSYM   200001
#define PADID  200000
#define BQ     1024
#define FEW    5
#define NB     200
#define DM     256     // D_MODEL
#define DI     512     // D_INNER
#define HID    512
#define G4     2048    // 4*HID
#define NROWS  (BQ + FEW)   // 1029 encoder rows (queries then supports)

// ---------------- device scratch (module globals; no runtime alloc) ---------
__device__ float g_proj[(size_t)NSYM * 256];   // [sym][0:128]=A-proj(+bias), [128:256]=B-proj
__device__ float g_Wproj[256 * 128];
__device__ float g_biasproj[256];
__device__ float g_bsum[G4];                   // b_ih + b_hh
__device__ float g_xcat[NROWS * DM];           // neighbor-encoder outputs (query rows 0..1023, support 1024..1028)
__device__ float g_henc[NROWS * DI];
__device__ float g_oenc[NROWS * DM];
__device__ float g_enc[NROWS * DM];            // layernorm output (query_g rows 0..1023)
__device__ float g_support[DM];                // support_g (1x256)
__device__ float g_sconst[G4];                 // support_g @ W_hh[:,256:]^T
__device__ float g_qWihb[BQ * G4];             // query_g @ W_ih^T + b_ih + b_hh
__device__ float g_gates[BQ * G4];
__device__ float g_h[BQ * DM];
__device__ float g_c[BQ * HID];
__device__ int   g_is64;

// ---------------- dtype detection for connection arrays ----------------
// If int64: odd 32-bit words of row 0 are high words of values < 2^31 -> all 0.
// If int32: those words are ent values incl. PAD=200000 -> guaranteed nonzero.
__global__ void detect_kernel(const int* qlc_i32) {
    if (blockIdx.x == 0 && threadIdx.x == 0) {
        int any = 0;
        for (int i = 1; i < 2 * NB; i += 2) any |= qlc_i32[i];
        g_is64 = (any == 0) ? 1 : 0;
    }
}

// ---------------- weight prep ----------------
__global__ void prep_kernel(const float* __restrict__ gcnW,
                            const float* __restrict__ wb,
                            const float* __restrict__ gb,
                            const float* __restrict__ bih,
                            const float* __restrict__ bhh) {
    int idx = blockIdx.x * blockDim.x + threadIdx.x;
    if (idx < 256 * 128) {
        int j = idx >> 7, e = idx & 127;
        g_Wproj[idx] = (j < 128) ? gcnW[j * 256 + e]
                                 : gcnW[(j - 128) * 256 + 128 + e];
    }
    if (idx < 256) g_biasproj[idx] = (idx < 128) ? (wb[idx] + gb[idx]) : 0.f;
    if (idx < G4)  g_bsum[idx] = bih[idx] + bhh[idx];
}

// ---------------- generic fp32 GEMM: C[M,N] = A[M,K] @ W[N,K]^T (+bias, +addMat, relu) ---
__global__ void __launch_bounds__(256)
gemm_tn(int M, int N, int K,
        const float* __restrict__ A, int lda,
        const float* __restrict__ W, int ldw,
        const float* __restrict__ bias,    // len N or null
        const float* __restrict__ addMat,  // [M,ldc] or null
        float* __restrict__ C, int ldc, int doRelu) {
    const int BK = 16;
    __shared__ float As[16][128];
    __shared__ float Bs[16][64];
    int tid = threadIdx.x;
    int bm = blockIdx.y * 128;
    int bn = blockIdx.x * 64;
    int tx = tid & 15, ty = tid >> 4;
    float acc[8][4] = {};

    for (int k0 = 0; k0 < K; k0 += BK) {
#pragma unroll
        for (int r = 0; r < 2; ++r) {
            int id  = tid + 256 * r;
            int row = id >> 2;
            int kq  = (id & 3) << 2;
            float4 v = make_float4(0.f, 0.f, 0.f, 0.f);
            int gr = bm + row;
            if (gr < M) v = *reinterpret_cast<const float4*>(A + (size_t)gr * lda + (k0 + kq));
            As[kq + 0][row] = v.x; As[kq + 1][row] = v.y;
            As[kq + 2][row] = v.z; As[kq + 3][row] = v.w;
        }
        {
            int row = tid >> 2;
            int kq  = (tid & 3) << 2;
            float4 v = make_float4(0.f, 0.f, 0.f, 0.f);
            int gr = bn + row;
            if (gr < N) v = *reinterpret_cast<const float4*>(W + (size_t)gr * ldw + (k0 + kq));
            Bs[kq + 0][row] = v.x; Bs[kq + 1][row] = v.y;
            Bs[kq + 2][row] = v.z; Bs[kq + 3][row] = v.w;
        }
        __syncthreads();
#pragma unroll
        for (int kk = 0; kk < BK; ++kk) {
            float4 a0 = *reinterpret_cast<const float4*>(&As[kk][ty * 8]);
            float4 a1 = *reinterpret_cast<const float4*>(&As[kk][ty * 8 + 4]);
            float4 b0 = *reinterpret_cast<const float4*>(&Bs[kk][tx * 4]);
            float a[8] = {a0.x, a0.y, a0.z, a0.w, a1.x, a1.y, a1.z, a1.w};
            float b[4] = {b0.x, b0.y, b0.z, b0.w};
#pragma unroll
            for (int i = 0; i < 8; ++i)
#pragma unroll
                for (int j = 0; j < 4; ++j)
                    acc[i][j] = fmaf(a[i], b[j], acc[i][j]);
        }
        __syncthreads();
    }

#pragma unroll
    for (int i = 0; i < 8; ++i) {
        int m = bm + ty * 8 + i;
        if (m >= M) continue;
#pragma unroll
        for (int j = 0; j < 4; ++j) {
            int n = bn + tx * 4 + j;
            if (n >= N) continue;
            float v = acc[i][j];
            if (bias)   v += bias[n];
            if (addMat) v += addMat[(size_t)m * ldc + n];
            if (doRelu) v = fmaxf(v, 0.f);
            C[(size_t)m * ldc + n] = v;
        }
    }
}

// ---------------- neighbor encoder: gather + leaky-relu + max + tanh -------
__global__ void __launch_bounds__(128)
neighbor_kernel(const void* qlc, const void* qrc, const void* slc, const void* src) {
    __shared__ int sidx[2 * NB];
    int b = blockIdx.x;
    const void* conn;
    int node;
    float* out;
    if (b < BQ)                { conn = qlc; node = b;              out = g_xcat + node * DM; }
    else if (b < 2 * BQ)       { conn = qrc; node = b - BQ;         out = g_xcat + node * DM + 128; }
    else if (b < 2 * BQ + FEW) { conn = slc; node = b - 2 * BQ;     out = g_xcat + (BQ + node) * DM; }
    else                       { conn = src; node = b - 2 * BQ - FEW; out = g_xcat + (BQ + node) * DM + 128; }

    int tid = threadIdx.x;
    size_t base = (size_t)node * (2 * NB);
    if (g_is64) {
        const long long* p = (const long long*)conn;
        for (int t = tid; t < 2 * NB; t += 128) sidx[t] = (int)p[base + t];
    } else {
        const int* p = (const int*)conn;
        for (int t = tid; t < 2 * NB; t += 128) sidx[t] = p[base + t];
    }
    __syncthreads();

    const float* __restrict__ proj = g_proj;
    float m = -INFINITY;
#pragma unroll 2
    for (int k = 0; k < NB; ++k) {
        int rel = sidx[2 * k], ent = sidx[2 * k + 1];
        if (rel == PADID || ent == PADID) continue;
        float v = proj[rel * 256 + tid] + proj[ent * 256 + 128 + tid];
        v = (v > 0.f) ? v : 0.1f * v;   // leaky_relu(0.1)
        m = fmaxf(m, v);
    }
    out[tid] = tanhf(m);
}

// ---------------- layernorm (per row of 256) ----------------
__global__ void ln_kernel(const float* __restrict__ lg, const float* __restrict__ lb) {
    __shared__ float red[256];
    int row = blockIdx.x, t = threadIdx.x;
    float v = g_oenc[row * DM + t];
    red[t] = v;
    __syncthreads();
    for (int s = 128; s > 0; s >>= 1) { if (t < s) red[t] += red[t + s]; __syncthreads(); }
    float mu = red[0] * (1.f / 256.f);
    __syncthreads();
    float d = v - mu;
    red[t] = d * d;
    __syncthreads();
    for (int s = 128; s > 0; s >>= 1) { if (t < s) red[t] += red[t + s]; __syncthreads(); }
    float var = red[0] * (1.f / 256.f);
    g_enc[row * DM + t] = d * rsqrtf(var + 1e-5f) * lg[t] + lb[t];
}

// ---------------- support_g = mean over the 5 support rows ----------------
__global__ void mean_kernel() {
    int t = threadIdx.x;
    float s = 0.f;
    for (int r = 0; r < FEW; ++r) s += g_enc[(BQ + r) * DM + t];
    g_support[t] = s * (1.f / FEW);
}

// ---------------- sconst[g] = support_g . W_hh[g, 256:512] ----------------
__global__ void sconst_kernel(const float* __restrict__ Whh) {
    int gidx = (blockIdx.x * blockDim.x + threadIdx.x) >> 5;
    int lane = threadIdx.x & 31;
    if (gidx >= G4) return;
    float s = 0.f;
    for (int i = lane; i < DM; i += 32)
        s += g_support[i] * Whh[(size_t)gidx * 512 + 256 + i];
#pragma unroll
    for (int o = 16; o > 0; o >>= 1) s += __shfl_down_sync(0xffffffffu, s, o);
    if (lane == 0) g_sconst[gidx] = s;
}

// ---------------- LSTM elementwise step ----------------
__device__ __forceinline__ float sigm(float x) { return 1.f / (1.f + expf(-x)); }

__global__ void lstm_kernel(const float* __restrict__ G, int firstStep) {
    int idx = blockIdx.x * blockDim.x + threadIdx.x;
    if (idx >= BQ * HID) return;
    int n = idx >> 9, j = idx & 511;
    const float* g = G + (size_t)n * G4;
    float gi = g[j], gf = g[512 + j], gg = g[1024 + j], go = g[1536 + j];
    float c  = firstStep ? 0.f : g_c[idx];
    float cn = sigm(gf) * c + sigm(gi) * tanhf(gg);
    g_c[idx] = cn;
    if (j < DM) {
        float hn = sigm(go) * tanhf(cn);
        g_h[n * DM + j] = g_enc[n * DM + j] + hn;   // h = query_g + h_new[:, :256]
    }
}

// ---------------- final: out[n] = h[n] . support_g ----------------
__global__ void final_kernel(float* __restrict__ out) {
    int n = (blockIdx.x * blockDim.x + threadIdx.x) >> 5;
    int lane = threadIdx.x & 31;
    if (n >= BQ) return;
    float s = 0.f;
    for (int i = lane; i < DM; i += 32)
        s += g_h[n * DM + i] * g_support[i];
#pragma unroll
    for (int o = 16; o > 0; o >>= 1) s += __shfl_down_sync(0xffffffffu, s, o);
    if (lane == 0) out[n] = s;
}

// ---------------- launch ----------------
extern "C" void kernel_launch(void* const* d_in, const int* in_sizes, int n_in,
                              void* d_out, int out_size) {
    const void* qlc = d_in[0];
    const void* qrc = d_in[1];
    const void* slc = d_in[2];
    const void* src = d_in[3];
    // d_in[4..7] = degrees (unused by the reference math)
    const float* emb  = (const float*)d_in[8];
    const float* gcnW = (const float*)d_in[9];
    const float* wb   = (const float*)d_in[10];
    const float* gb   = (const float*)d_in[11];
    const float* p1W  = (const float*)d_in[12];
    const float* p1b  = (const float*)d_in[13];
    const float* p2W  = (const float*)d_in[14];
    const float* p2b  = (const float*)d_in[15];
    const float* lng  = (const float*)d_in[16];
    const float* lnb  = (const float*)d_in[17];
    const float* Wih  = (const float*)d_in[18];
    const float* Whh  = (const float*)d_in[19];
    const float* bih  = (const float*)d_in[20];
    const float* bhh  = (const float*)d_in[21];

    float *proj, *Wproj, *biasproj, *bsum, *xcat, *henc, *oenc, *enc, *sconst, *qWihb, *gates, *h;
    cudaGetSymbolAddress((void**)&proj,     g_proj);
    cudaGetSymbolAddress((void**)&Wproj,    g_Wproj);
    cudaGetSymbolAddress((void**)&biasproj, g_biasproj);
    cudaGetSymbolAddress((void**)&bsum,     g_bsum);
    cudaGetSymbolAddress((void**)&xcat,     g_xcat);
    cudaGetSymbolAddress((void**)&henc,     g_henc);
    cudaGetSymbolAddress((void**)&oenc,     g_oenc);
    cudaGetSymbolAddress((void**)&enc,      g_enc);
    cudaGetSymbolAddress((void**)&sconst,   g_sconst);
    cudaGetSymbolAddress((void**)&qWihb,    g_qWihb);
    cudaGetSymbolAddress((void**)&gates,    g_gates);
    cudaGetSymbolAddress((void**)&h,        g_h);

    detect_kernel<<<1, 1>>>((const int*)qlc);
    prep_kernel<<<128, 256>>>(gcnW, wb, gb, bih, bhh);

    // projected embedding table: g_proj = emb @ Wproj^T (+bias on first half)
    gemm_tn<<<dim3(256 / 64, (NSYM + 127) / 128), 256>>>(
        NSYM, 256, 128, emb, 128, Wproj, 128, biasproj, nullptr, proj, 256, 0);

    // neighbor encoder (gather + max) for queries (left/right) and supports
    neighbor_kernel<<<2 * BQ + 2 * FEW, 128>>>(qlc, qrc, slc, src);

    // support encoder (batched over 1029 rows): relu(x@p1W^T+p1b) -> @p2W^T+p2b+x -> LN
    gemm_tn<<<dim3(512 / 64, (NROWS + 127) / 128), 256>>>(
        NROWS, 512, 256, xcat, 256, p1W, 256, p1b, nullptr, henc, 512, 1);
    gemm_tn<<<dim3(256 / 64, (NROWS + 127) / 128), 256>>>(
        NROWS, 256, 512, henc, 512, p2W, 512, p2b, xcat, oenc, 256, 0);
    ln_kernel<<<NROWS, 256>>>(lng, lnb);

    mean_kernel<<<1, 256>>>();
    sconst_kernel<<<G4 * 32 / 256, 256>>>(Whh);

    // step-invariant gate term: query_g @ W_ih^T + b_ih + b_hh
    gemm_tn<<<dim3(G4 / 64, BQ / 128), 256>>>(
        BQ, G4, 256, enc, 256, Wih, 256, bsum, nullptr, qWihb, G4, 0);

    // step 1: h_r = 0 -> gates are just qWihb
    lstm_kernel<<<(BQ * HID + 255) / 256, 256>>>(qWihb, 1);

    // steps 2..4: gates = h @ W_hh[:, :256]^T + sconst + qWihb
    for (int s = 1; s < 4; ++s) {
        gemm_tn<<<dim3(G4 / 64, BQ / 128), 256>>>(
            BQ, G4, 256, h, 256, Whh, 512, sconst, qWihb, gates, G4, 0);
        lstm_kernel<<<(BQ * HID + 255) / 256, 256>>>(gates, 0);
    }

    final_kernel<<<(BQ * 32 + 255) / 256, 256>>>((float*)d_out);
}

// round 5
// speedup vs baseline: 1.4062x; 1.4062x over previous
#include <cuda_runtime.h>
#include <cuda_bf16.h>
#include <cstdint>
#include <math.h>

// ---------------- problem constants ----------------
#define NSYM   200001
#define PADID  200000
#define BQ     1024
#define FEW    5
#define NB     200
#define DM     256     // D_MODEL
#define DI     512     // D_INNER
#define HID    512
#define G4     2048    // 4*HID
#define NROWS  (BQ + FEW)   // 1029 encoder rows (queries then supports)

// ---------------- device scratch (module globals; no runtime alloc) ---------
__device__ float g_proj[(size_t)NSYM * 256];   // [sym][0:128]=A-proj(+bias), [128:256]=B-proj
__device__ float g_Wproj[256 * 128];
__device__ float g_biasproj[256];
__device__ float g_bsum[G4];                   // b_ih + b_hh
__device__ float g_xcat[NROWS * DM];
__device__ float g_henc[NROWS * DI];
__device__ float g_oenc[NROWS * DM];
__device__ float g_enc[NROWS * DM];
__device__ float g_support[DM];
__device__ float g_sconst[G4];
__device__ float g_qWihb[BQ * G4];
__device__ float g_gates[BQ * G4];
__device__ float g_h[BQ * DM];
__device__ float g_c[BQ * HID];
__device__ int   g_is64;

// ---------------- dtype detection for connection arrays ----------------
__global__ void detect_kernel(const int* qlc_i32) {
    if (blockIdx.x == 0 && threadIdx.x == 0) {
        int any = 0;
        for (int i = 1; i < 2 * NB; i += 2) any |= qlc_i32[i];
        g_is64 = (any == 0) ? 1 : 0;
    }
}

// ---------------- weight prep ----------------
__global__ void prep_kernel(const float* __restrict__ gcnW,
                            const float* __restrict__ wb,
                            const float* __restrict__ gb,
                            const float* __restrict__ bih,
                            const float* __restrict__ bhh) {
    int idx = blockIdx.x * blockDim.x + threadIdx.x;
    if (idx < 256 * 128) {
        int j = idx >> 7, e = idx & 127;
        g_Wproj[idx] = (j < 128) ? gcnW[j * 256 + e]
                                 : gcnW[(j - 128) * 256 + 128 + e];
    }
    if (idx < 256) g_biasproj[idx] = (idx < 128) ? (wb[idx] + gb[idx]) : 0.f;
    if (idx < G4)  g_bsum[idx] = bih[idx] + bhh[idx];
}

// =====================================================================
// HMMA (mma.sync bf16) 3-pass split projection GEMM:
//   g_proj[NSYM,256] = emb[NSYM,128] @ Wproj[256,128]^T  (+ bias)
// fp32 ~= hi*hi + hi*lo + lo*hi in bf16, fp32 accumulation.
// Per CTA: M=128, N=256, K=128. 512 threads = 4(M)x4(N) warps,
// each warp a 32x64 output tile.
// =====================================================================

#define LDS_STRIDE 136                       // bf16 elems per smem row (128 + 8 pad)
#define ROWB (LDS_STRIDE * 2)                // 272 bytes per row
#define AH_OFF 0
#define AL_OFF (128 * ROWB)                  // 34816
#define BH_OFF (2 * 128 * ROWB)              // 69632
#define BL_OFF (BH_OFF + 256 * ROWB)         // 139264
#define PROJ_SMEM (BH_OFF + 2 * 256 * ROWB)  // 208896 bytes

__device__ __forceinline__ uint32_t smem_u32(const void* p) {
    uint32_t a;
    asm("{ .reg .u64 t; cvta.to.shared.u64 t, %1; cvt.u32.u64 %0, t; }" : "=r"(a) : "l"(p));
    return a;
}

__device__ __forceinline__ void ldmatrix4(uint32_t addr, uint32_t& r0, uint32_t& r1,
                                          uint32_t& r2, uint32_t& r3) {
    asm volatile("ldmatrix.sync.aligned.m8n8.x4.shared.b16 {%0,%1,%2,%3}, [%4];"
                 : "=r"(r0), "=r"(r1), "=r"(r2), "=r"(r3) : "r"(addr));
}

__device__ __forceinline__ void mma16816(float* d, const uint32_t* a,
                                         uint32_t b0, uint32_t b1) {
    asm volatile(
        "mma.sync.aligned.m16n8k16.row.col.f32.bf16.bf16.f32 "
        "{%0,%1,%2,%3}, {%4,%5,%6,%7}, {%8,%9}, {%0,%1,%2,%3};"
        : "+f"(d[0]), "+f"(d[1]), "+f"(d[2]), "+f"(d[3])
        : "r"(a[0]), "r"(a[1]), "r"(a[2]), "r"(a[3]), "r"(b0), "r"(b1));
}

__device__ __forceinline__ uint32_t pack_bf2(__nv_bfloat16 a, __nv_bfloat16 b) {
    __nv_bfloat162 t(a, b);
    return *reinterpret_cast<uint32_t*>(&t);
}

// split 8 floats into packed bf16 hi / lo uint4s
__device__ __forceinline__ void split8(const float* f, uint4& hi, uint4& lo) {
    __nv_bfloat16 h[8], l[8];
#pragma unroll
    for (int i = 0; i < 8; ++i) {
        h[i] = __float2bfloat16(f[i]);
        l[i] = __float2bfloat16(f[i] - __bfloat162float(h[i]));
    }
    hi = make_uint4(pack_bf2(h[0], h[1]), pack_bf2(h[2], h[3]),
                    pack_bf2(h[4], h[5]), pack_bf2(h[6], h[7]));
    lo = make_uint4(pack_bf2(l[0], l[1]), pack_bf2(l[2], l[3]),
                    pack_bf2(l[4], l[5]), pack_bf2(l[6], l[7]));
}

__global__ void __launch_bounds__(512, 1)
proj_mma_kernel(const float* __restrict__ emb) {
    extern __shared__ char sm[];
    const uint32_t sbase = smem_u32(sm);
    const int tid = threadIdx.x;
    const int mbase = blockIdx.x * 128;

    // ---- load + split A tile (128 x 128 fp32 -> bf16 hi/lo) ----
#pragma unroll
    for (int i = 0; i < 4; ++i) {
        int c = tid + i * 512;
        int row = c >> 4, ch = c & 15;
        int grow = mbase + row;
        float f[8] = {0.f, 0.f, 0.f, 0.f, 0.f, 0.f, 0.f, 0.f};
        if (grow < NSYM) {
            const float4* p = reinterpret_cast<const float4*>(emb + (size_t)grow * 128 + ch * 8);
            float4 v0 = p[0], v1 = p[1];
            f[0] = v0.x; f[1] = v0.y; f[2] = v0.z; f[3] = v0.w;
            f[4] = v1.x; f[5] = v1.y; f[6] = v1.z; f[7] = v1.w;
        }
        uint4 hi, lo;
        split8(f, hi, lo);
        int off = row * ROWB + ch * 16;
        *reinterpret_cast<uint4*>(sm + AH_OFF + off) = hi;
        *reinterpret_cast<uint4*>(sm + AL_OFF + off) = lo;
    }

    // ---- load + split B tile (256 x 128 fp32 = Wproj) ----
#pragma unroll
    for (int i = 0; i < 8; ++i) {
        int c = tid + i * 512;
        int row = c >> 4, ch = c & 15;
        const float4* p = reinterpret_cast<const float4*>(g_Wproj + row * 128 + ch * 8);
        float4 v0 = p[0], v1 = p[1];
        float f[8] = {v0.x, v0.y, v0.z, v0.w, v1.x, v1.y, v1.z, v1.w};
        uint4 hi, lo;
        split8(f, hi, lo);
        int off = row * ROWB + ch * 16;
        *reinterpret_cast<uint4*>(sm + BH_OFF + off) = hi;
        *reinterpret_cast<uint4*>(sm + BL_OFF + off) = lo;
    }
    __syncthreads();

    const int warp = tid >> 5, lane = tid & 31;
    const int wm = warp & 3, wn = warp >> 2;   // 4x4 warp grid
    const int m0 = wm * 32, n0 = wn * 64;

    float acc[2][8][4];
#pragma unroll
    for (int i = 0; i < 2; ++i)
#pragma unroll
        for (int j = 0; j < 8; ++j)
#pragma unroll
            for (int q = 0; q < 4; ++q) acc[i][j][q] = 0.f;

    // precomputed intra-fragment address components
    const int a_row = (lane & 15);
    const int a_kadd = (lane >> 4) << 3;                 // 0 or 8
    const int b_row = ((lane >> 4) << 3) + (lane & 7);   // 0..15
    const int b_kadd = ((lane >> 3) & 1) << 3;           // 0 or 8

    for (int pass = 0; pass < 3; ++pass) {
        const uint32_t Abase = sbase + ((pass == 2) ? AL_OFF : AH_OFF);
        const uint32_t Bbase = sbase + ((pass == 1) ? BL_OFF : BH_OFF);
#pragma unroll
        for (int ks = 0; ks < 8; ++ks) {
            const int k0 = ks * 16;
            uint32_t ra[2][4];
#pragma unroll
            for (int mi = 0; mi < 2; ++mi) {
                uint32_t addr = Abase + (m0 + mi * 16 + a_row) * ROWB + (k0 + a_kadd) * 2;
                ldmatrix4(addr, ra[mi][0], ra[mi][1], ra[mi][2], ra[mi][3]);
            }
            uint32_t rb[4][4];
#pragma unroll
            for (int np = 0; np < 4; ++np) {
                uint32_t addr = Bbase + (n0 + np * 16 + b_row) * ROWB + (k0 + b_kadd) * 2;
                ldmatrix4(addr, rb[np][0], rb[np][1], rb[np][2], rb[np][3]);
            }
#pragma unroll
            for (int mi = 0; mi < 2; ++mi)
#pragma unroll
                for (int ni = 0; ni < 8; ++ni) {
                    uint32_t b0 = rb[ni >> 1][(ni & 1) * 2 + 0];
                    uint32_t b1 = rb[ni >> 1][(ni & 1) * 2 + 1];
                    mma16816(acc[mi][ni], ra[mi], b0, b1);
                }
        }
    }

    // ---- epilogue: accum -> g_proj with bias add ----
    const int rbase = mbase + m0;
#pragma unroll
    for (int mi = 0; mi < 2; ++mi) {
#pragma unroll
        for (int ni = 0; ni < 8; ++ni) {
            int col = n0 + ni * 8 + (lane & 3) * 2;
            float b0 = g_biasproj[col], b1 = g_biasproj[col + 1];
            int r0 = rbase + mi * 16 + (lane >> 2);
            int r1 = r0 + 8;
            if (r0 < NSYM) {
                float2 o = make_float2(acc[mi][ni][0] + b0, acc[mi][ni][1] + b1);
                *reinterpret_cast<float2*>(g_proj + (size_t)r0 * 256 + col) = o;
            }
            if (r1 < NSYM) {
                float2 o = make_float2(acc[mi][ni][2] + b0, acc[mi][ni][3] + b1);
                *reinterpret_cast<float2*>(g_proj + (size_t)r1 * 256 + col) = o;
            }
        }
    }
}

// ---------------- generic fp32 GEMM: C[M,N] = A[M,K] @ W[N,K]^T (+bias, +addMat, relu) ---
__global__ void __launch_bounds__(256)
gemm_tn(int M, int N, int K,
        const float* __restrict__ A, int lda,
        const float* __restrict__ W, int ldw,
        const float* __restrict__ bias,
        const float* __restrict__ addMat,
        float* __restrict__ C, int ldc, int doRelu) {
    const int BK = 16;
    __shared__ float As[16][128];
    __shared__ float Bs[16][64];
    int tid = threadIdx.x;
    int bm = blockIdx.y * 128;
    int bn = blockIdx.x * 64;
    int tx = tid & 15, ty = tid >> 4;
    float acc[8][4] = {};

    for (int k0 = 0; k0 < K; k0 += BK) {
#pragma unroll
        for (int r = 0; r < 2; ++r) {
            int id  = tid + 256 * r;
            int row = id >> 2;
            int kq  = (id & 3) << 2;
            float4 v = make_float4(0.f, 0.f, 0.f, 0.f);
            int gr = bm + row;
            if (gr < M) v = *reinterpret_cast<const float4*>(A + (size_t)gr * lda + (k0 + kq));
            As[kq + 0][row] = v.x; As[kq + 1][row] = v.y;
            As[kq + 2][row] = v.z; As[kq + 3][row] = v.w;
        }
        {
            int row = tid >> 2;
            int kq  = (tid & 3) << 2;
            float4 v = make_float4(0.f, 0.f, 0.f, 0.f);
            int gr = bn + row;
            if (gr < N) v = *reinterpret_cast<const float4*>(W + (size_t)gr * ldw + (k0 + kq));
            Bs[kq + 0][row] = v.x; Bs[kq + 1][row] = v.y;
            Bs[kq + 2][row] = v.z; Bs[kq + 3][row] = v.w;
        }
        __syncthreads();
#pragma unroll
        for (int kk = 0; kk < BK; ++kk) {
            float4 a0 = *reinterpret_cast<const float4*>(&As[kk][ty * 8]);
            float4 a1 = *reinterpret_cast<const float4*>(&As[kk][ty * 8 + 4]);
            float4 b0 = *reinterpret_cast<const float4*>(&Bs[kk][tx * 4]);
            float a[8] = {a0.x, a0.y, a0.z, a0.w, a1.x, a1.y, a1.z, a1.w};
            float b[4] = {b0.x, b0.y, b0.z, b0.w};
#pragma unroll
            for (int i = 0; i < 8; ++i)
#pragma unroll
                for (int j = 0; j < 4; ++j)
                    acc[i][j] = fmaf(a[i], b[j], acc[i][j]);
        }
        __syncthreads();
    }

#pragma unroll
    for (int i = 0; i < 8; ++i) {
        int m = bm + ty * 8 + i;
        if (m >= M) continue;
#pragma unroll
        for (int j = 0; j < 4; ++j) {
            int n = bn + tx * 4 + j;
            if (n >= N) continue;
            float v = acc[i][j];
            if (bias)   v += bias[n];
            if (addMat) v += addMat[(size_t)m * ldc + n];
            if (doRelu) v = fmaxf(v, 0.f);
            C[(size_t)m * ldc + n] = v;
        }
    }
}

// ---------------- neighbor encoder: gather + leaky-relu + max + tanh -------
__global__ void __launch_bounds__(128)
neighbor_kernel(const void* qlc, const void* qrc, const void* slc, const void* src) {
    __shared__ int sidx[2 * NB];
    int b = blockIdx.x;
    const void* conn;
    int node;
    float* out;
    if (b < BQ)                { conn = qlc; node = b;              out = g_xcat + node * DM; }
    else if (b < 2 * BQ)       { conn = qrc; node = b - BQ;         out = g_xcat + node * DM + 128; }
    else if (b < 2 * BQ + FEW) { conn = slc; node = b - 2 * BQ;     out = g_xcat + (BQ + node) * DM; }
    else                       { conn = src; node = b - 2 * BQ - FEW; out = g_xcat + (BQ + node) * DM + 128; }

    int tid = threadIdx.x;
    size_t base = (size_t)node * (2 * NB);
    if (g_is64) {
        const long long* p = (const long long*)conn;
        for (int t = tid; t < 2 * NB; t += 128) sidx[t] = (int)p[base + t];
    } else {
        const int* p = (const int*)conn;
        for (int t = tid; t < 2 * NB; t += 128) sidx[t] = p[base + t];
    }
    __syncthreads();

    const float* __restrict__ proj = g_proj;
    float m = -INFINITY;
#pragma unroll 2
    for (int k = 0; k < NB; ++k) {
        int rel = sidx[2 * k], ent = sidx[2 * k + 1];
        if (rel == PADID || ent == PADID) continue;
        float v = proj[rel * 256 + tid] + proj[ent * 256 + 128 + tid];
        v = (v > 0.f) ? v : 0.1f * v;   // leaky_relu(0.1)
        m = fmaxf(m, v);
    }
    out[tid] = tanhf(m);
}

// ---------------- layernorm (per row of 256) ----------------
__global__ void ln_kernel(const float* __restrict__ lg, const float* __restrict__ lb) {
    __shared__ float red[256];
    int row = blockIdx.x, t = threadIdx.x;
    float v = g_oenc[row * DM + t];
    red[t] = v;
    __syncthreads();
    for (int s = 128; s > 0; s >>= 1) { if (t < s) red[t] += red[t + s]; __syncthreads(); }
    float mu = red[0] * (1.f / 256.f);
    __syncthreads();
    float d = v - mu;
    red[t] = d * d;
    __syncthreads();
    for (int s = 128; s > 0; s >>= 1) { if (t < s) red[t] += red[t + s]; __syncthreads(); }
    float var = red[0] * (1.f / 256.f);
    g_enc[row * DM + t] = d * rsqrtf(var + 1e-5f) * lg[t] + lb[t];
}

// ---------------- support_g = mean over the 5 support rows ----------------
__global__ void mean_kernel() {
    int t = threadIdx.x;
    float s = 0.f;
    for (int r = 0; r < FEW; ++r) s += g_enc[(BQ + r) * DM + t];
    g_support[t] = s * (1.f / FEW);
}

// ---------------- sconst[g] = support_g . W_hh[g, 256:512] ----------------
__global__ void sconst_kernel(const float* __restrict__ Whh) {
    int gidx = (blockIdx.x * blockDim.x + threadIdx.x) >> 5;
    int lane = threadIdx.x & 31;
    if (gidx >= G4) return;
    float s = 0.f;
    for (int i = lane; i < DM; i += 32)
        s += g_support[i] * Whh[(size_t)gidx * 512 + 256 + i];
#pragma unroll
    for (int o = 16; o > 0; o >>= 1) s += __shfl_down_sync(0xffffffffu, s, o);
    if (lane == 0) g_sconst[gidx] = s;
}

// ---------------- LSTM elementwise step ----------------
__device__ __forceinline__ float sigm(float x) { return 1.f / (1.f + expf(-x)); }

__global__ void lstm_kernel(const float* __restrict__ G, int firstStep) {
    int idx = blockIdx.x * blockDim.x + threadIdx.x;
    if (idx >= BQ * HID) return;
    int n = idx >> 9, j = idx & 511;
    const float* g = G + (size_t)n * G4;
    float gi = g[j], gf = g[512 + j], gg = g[1024 + j], go = g[1536 + j];
    float c  = firstStep ? 0.f : g_c[idx];
    float cn = sigm(gf) * c + sigm(gi) * tanhf(gg);
    g_c[idx] = cn;
    if (j < DM) {
        float hn = sigm(go) * tanhf(cn);
        g_h[n * DM + j] = g_enc[n * DM + j] + hn;
    }
}

// ---------------- final: out[n] = h[n] . support_g ----------------
__global__ void final_kernel(float* __restrict__ out) {
    int n = (blockIdx.x * blockDim.x + threadIdx.x) >> 5;
    int lane = threadIdx.x & 31;
    if (n >= BQ) return;
    float s = 0.f;
    for (int i = lane; i < DM; i += 32)
        s += g_h[n * DM + i] * g_support[i];
#pragma unroll
    for (int o = 16; o > 0; o >>= 1) s += __shfl_down_sync(0xffffffffu, s, o);
    if (lane == 0) out[n] = s;
}

// ---------------- launch ----------------
extern "C" void kernel_launch(void* const* d_in, const int* in_sizes, int n_in,
                              void* d_out, int out_size) {
    const void* qlc = d_in[0];
    const void* qrc = d_in[1];
    const void* slc = d_in[2];
    const void* src = d_in[3];
    const float* emb  = (const float*)d_in[8];
    const float* gcnW = (const float*)d_in[9];
    const float* wb   = (const float*)d_in[10];
    const float* gb   = (const float*)d_in[11];
    const float* p1W  = (const float*)d_in[12];
    const float* p1b  = (const float*)d_in[13];
    const float* p2W  = (const float*)d_in[14];
    const float* p2b  = (const float*)d_in[15];
    const float* lng  = (const float*)d_in[16];
    const float* lnb  = (const float*)d_in[17];
    const float* Wih  = (const float*)d_in[18];
    const float* Whh  = (const float*)d_in[19];
    const float* bih  = (const float*)d_in[20];
    const float* bhh  = (const float*)d_in[21];

    float *xcat, *henc, *oenc, *enc, *sconst, *qWihb, *gates, *h, *bsum;
    cudaGetSymbolAddress((void**)&xcat,   g_xcat);
    cudaGetSymbolAddress((void**)&henc,   g_henc);
    cudaGetSymbolAddress((void**)&oenc,   g_oenc);
    cudaGetSymbolAddress((void**)&enc,    g_enc);
    cudaGetSymbolAddress((void**)&sconst, g_sconst);
    cudaGetSymbolAddress((void**)&qWihb,  g_qWihb);
    cudaGetSymbolAddress((void**)&gates,  g_gates);
    cudaGetSymbolAddress((void**)&h,      g_h);
    cudaGetSymbolAddress((void**)&bsum,   g_bsum);

    detect_kernel<<<1, 1>>>((const int*)qlc);
    prep_kernel<<<128, 256>>>(gcnW, wb, gb, bih, bhh);

    // HMMA bf16-split projection GEMM: g_proj = emb @ Wproj^T (+bias)
    cudaFuncSetAttribute(proj_mma_kernel,
                         cudaFuncAttributeMaxDynamicSharedMemorySize, PROJ_SMEM);
    proj_mma_kernel<<<(NSYM + 127) / 128, 512, PROJ_SMEM>>>(emb);

    // neighbor encoder (gather + max)
    neighbor_kernel<<<2 * BQ + 2 * FEW, 128>>>(qlc, qrc, slc, src);

    // support encoder
    gemm_tn<<<dim3(512 / 64, (NROWS + 127) / 128), 256>>>(
        NROWS, 512, 256, xcat, 256, p1W, 256, p1b, nullptr, henc, 512, 1);
    gemm_tn<<<dim3(256 / 64, (NROWS + 127) / 128), 256>>>(
        NROWS, 256, 512, henc, 512, p2W, 512, p2b, xcat, oenc, 256, 0);
    ln_kernel<<<NROWS, 256>>>(lng, lnb);

    mean_kernel<<<1, 256>>>();
    sconst_kernel<<<G4 * 32 / 256, 256>>>(Whh);

    // step-invariant gate term: query_g @ W_ih^T + b_ih + b_hh
    gemm_tn<<<dim3(G4 / 64, BQ / 128), 256>>>(
        BQ, G4, 256, enc, 256, Wih, 256, bsum, nullptr, qWihb, G4, 0);

    // step 1: h_r = 0
    lstm_kernel<<<(BQ * HID + 255) / 256, 256>>>(qWihb, 1);

    // steps 2..4
    for (int s = 1; s < 4; ++s) {
        gemm_tn<<<dim3(G4 / 64, BQ / 128), 256>>>(
            BQ, G4, 256, h, 256, Whh, 512, sconst, qWihb, gates, G4, 0);
        lstm_kernel<<<(BQ * HID + 255) / 256, 256>>>(gates, 0);
    }

    final_kernel<<<(BQ * 32 + 255) / 256, 256>>>((float*)d_out);
}

// round 6
// speedup vs baseline: 1.5964x; 1.1352x over previous
#include <cuda_runtime.h>
#include <cuda_bf16.h>
#include <cstdint>
#include <math.h>

// ---------------- problem constants ----------------
#define NSYM   200001
#define PADID  200000
#define BQ     1024
#define FEW    5
#define NB     200
#define DM     256
#define DI     512
#define HID    512
#define G4     2048
#define NROWS  (BQ + FEW)

typedef __nv_bfloat16 bf16;

// ---------------- device scratch ----------------
__device__ float g_proj[(size_t)NSYM * 256];
__device__ bf16  g_embhi[(size_t)NSYM * 128];
__device__ bf16  g_emblo[(size_t)NSYM * 128];
__device__ bf16  g_Wphi[256 * 128], g_Wplo[256 * 128];
__device__ bf16  g_p1hi[512 * 256], g_p1lo[512 * 256];
__device__ bf16  g_p2hi[256 * 512], g_p2lo[256 * 512];
__device__ bf16  g_Wihhi[2048 * 256], g_Wihlo[2048 * 256];
__device__ bf16  g_Whhhi[2048 * 256], g_Whhlo[2048 * 256];
__device__ float g_biasproj[256];
__device__ float g_bsum[G4];
__device__ float g_xcat[NROWS * DM];
__device__ bf16  g_xcathi[NROWS * DM], g_xcatlo[NROWS * DM];
__device__ bf16  g_henchi[NROWS * DI], g_henclo[NROWS * DI];
__device__ float g_oenc[NROWS * DM];
__device__ float g_enc[NROWS * DM];
__device__ bf16  g_enchi[NROWS * DM], g_enclo[NROWS * DM];
__device__ float g_support[DM];
__device__ float g_sconst[G4];
__device__ float g_qWihb[BQ * G4];
__device__ float g_gates[BQ * G4];
__device__ float g_h[BQ * DM];
__device__ bf16  g_hhi[BQ * DM], g_hlo[BQ * DM];
__device__ float g_c[BQ * HID];
__device__ int   g_is64;

// ---------------- helpers ----------------
__device__ __forceinline__ uint32_t smem_u32(const void* p) {
    uint32_t a;
    asm("{ .reg .u64 t; cvta.to.shared.u64 t, %1; cvt.u32.u64 %0, t; }" : "=r"(a) : "l"(p));
    return a;
}
__device__ __forceinline__ void ldmatrix4(uint32_t addr, uint32_t& r0, uint32_t& r1,
                                          uint32_t& r2, uint32_t& r3) {
    asm volatile("ldmatrix.sync.aligned.m8n8.x4.shared.b16 {%0,%1,%2,%3}, [%4];"
                 : "=r"(r0), "=r"(r1), "=r"(r2), "=r"(r3) : "r"(addr));
}
__device__ __forceinline__ void mma16816(float* d, const uint32_t* a,
                                         uint32_t b0, uint32_t b1) {
    asm volatile(
        "mma.sync.aligned.m16n8k16.row.col.f32.bf16.bf16.f32 "
        "{%0,%1,%2,%3}, {%4,%5,%6,%7}, {%8,%9}, {%0,%1,%2,%3};"
        : "+f"(d[0]), "+f"(d[1]), "+f"(d[2]), "+f"(d[3])
        : "r"(a[0]), "r"(a[1]), "r"(a[2]), "r"(a[3]), "r"(b0), "r"(b1));
}
__device__ __forceinline__ uint32_t pack_bf2(bf16 a, bf16 b) {
    __nv_bfloat162 t(a, b);
    return *reinterpret_cast<uint32_t*>(&t);
}
__device__ __forceinline__ void split1(float v, bf16& h, bf16& l) {
    h = __float2bfloat16(v);
    l = __float2bfloat16(v - __bfloat162float(h));
}
__device__ __forceinline__ void split8(const float* f, uint4& hi, uint4& lo) {
    bf16 h[8], l[8];
#pragma unroll
    for (int i = 0; i < 8; ++i) split1(f[i], h[i], l[i]);
    hi = make_uint4(pack_bf2(h[0], h[1]), pack_bf2(h[2], h[3]),
                    pack_bf2(h[4], h[5]), pack_bf2(h[6], h[7]));
    lo = make_uint4(pack_bf2(l[0], l[1]), pack_bf2(l[2], l[3]),
                    pack_bf2(l[4], l[5]), pack_bf2(l[6], l[7]));
}

// ---------------- dtype detection ----------------
__global__ void detect_kernel(const int* qlc_i32) {
    if (blockIdx.x == 0 && threadIdx.x == 0) {
        int any = 0;
        for (int i = 1; i < 2 * NB; i += 2) any |= qlc_i32[i];
        g_is64 = (any == 0) ? 1 : 0;
    }
}

// ---------------- weight prep: Wproj reshuffle+split, biases ----------------
__global__ void prep_kernel(const float* __restrict__ gcnW,
                            const float* __restrict__ wb,
                            const float* __restrict__ gb,
                            const float* __restrict__ bih,
                            const float* __restrict__ bhh) {
    int idx = blockIdx.x * blockDim.x + threadIdx.x;
    if (idx < 256 * 128) {
        int j = idx >> 7, e = idx & 127;
        float v = (j < 128) ? gcnW[j * 256 + e] : gcnW[(j - 128) * 256 + 128 + e];
        bf16 h, l;
        split1(v, h, l);
        g_Wphi[idx] = h;
        g_Wplo[idx] = l;
    }
    if (idx < 256) g_biasproj[idx] = (idx < 128) ? (wb[idx] + gb[idx]) : 0.f;
    if (idx < G4)  g_bsum[idx] = bih[idx] + bhh[idx];
}

// ---------------- generic fp32 -> bf16 hi/lo split (vectorized x8) ----------
__global__ void split_w_kernel(const float* __restrict__ W, int total8, int K, int ldw,
                               bf16* __restrict__ hi, bf16* __restrict__ lo) {
    int i = blockIdx.x * blockDim.x + threadIdx.x;
    if (i >= total8) return;
    int e0 = i * 8;
    int row = e0 / K, col = e0 % K;
    const float* src = W + (size_t)row * ldw + col;
    float4 v0 = *reinterpret_cast<const float4*>(src);
    float4 v1 = *reinterpret_cast<const float4*>(src + 4);
    float f[8] = {v0.x, v0.y, v0.z, v0.w, v1.x, v1.y, v1.z, v1.w};
    uint4 h, l;
    split8(f, h, l);
    *reinterpret_cast<uint4*>(hi + e0) = h;
    *reinterpret_cast<uint4*>(lo + e0) = l;
}

// =====================================================================
// proj_mma v2: g_proj[NSYM,256] = emb @ Wproj^T (+bias)
// pre-split bf16 operands, 3-pass accumulation. CTA tile 128x256.
// =====================================================================
#define ROWB 272   // 256B data + 16B pad per 128-elem bf16 row
#define AH_OFF 0
#define AL_OFF (128 * ROWB)
#define BH_OFF (2 * 128 * ROWB)
#define BL_OFF (BH_OFF + 256 * ROWB)
#define PROJ_SMEM (BH_OFF + 2 * 256 * ROWB)   // 208896

__global__ void __launch_bounds__(512, 1)
proj_mma_kernel() {
    extern __shared__ char sm[];
    const uint32_t sbase = smem_u32(sm);
    const int tid = threadIdx.x;
    const int mbase = blockIdx.x * 128;

    // A tile: 128 rows x 128 bf16 (hi & lo): 2048 16B-chunks each
#pragma unroll
    for (int i = 0; i < 4; ++i) {
        int c = tid + i * 512;
        int row = c >> 4, ch = c & 15;
        int grow = mbase + row;
        uint4 h = make_uint4(0, 0, 0, 0), l = make_uint4(0, 0, 0, 0);
        if (grow < NSYM) {
            h = *reinterpret_cast<const uint4*>(g_embhi + (size_t)grow * 128 + ch * 8);
            l = *reinterpret_cast<const uint4*>(g_emblo + (size_t)grow * 128 + ch * 8);
        }
        int off = row * ROWB + ch * 16;
        *reinterpret_cast<uint4*>(sm + AH_OFF + off) = h;
        *reinterpret_cast<uint4*>(sm + AL_OFF + off) = l;
    }
    // B tile: 256 rows x 128 bf16 (hi & lo)
#pragma unroll
    for (int i = 0; i < 8; ++i) {
        int c = tid + i * 512;
        int row = c >> 4, ch = c & 15;
        uint4 h = *reinterpret_cast<const uint4*>(g_Wphi + row * 128 + ch * 8);
        uint4 l = *reinterpret_cast<const uint4*>(g_Wplo + row * 128 + ch * 8);
        int off = row * ROWB + ch * 16;
        *reinterpret_cast<uint4*>(sm + BH_OFF + off) = h;
        *reinterpret_cast<uint4*>(sm + BL_OFF + off) = l;
    }
    __syncthreads();

    const int warp = tid >> 5, lane = tid & 31;
    const int wm = warp & 3, wn = warp >> 2;
    const int m0 = wm * 32, n0 = wn * 64;

    float acc[2][8][4];
#pragma unroll
    for (int i = 0; i < 2; ++i)
#pragma unroll
        for (int j = 0; j < 8; ++j)
#pragma unroll
            for (int q = 0; q < 4; ++q) acc[i][j][q] = 0.f;

    const int a_row = (lane & 15);
    const int a_kadd = (lane >> 4) << 3;
    const int b_row = ((lane >> 4) << 3) + (lane & 7);
    const int b_kadd = ((lane >> 3) & 1) << 3;

    for (int pass = 0; pass < 3; ++pass) {
        const uint32_t Abase = sbase + ((pass == 2) ? AL_OFF : AH_OFF);
        const uint32_t Bbase = sbase + ((pass == 1) ? BL_OFF : BH_OFF);
#pragma unroll
        for (int ks = 0; ks < 8; ++ks) {
            const int k0 = ks * 16;
            uint32_t ra[2][4];
#pragma unroll
            for (int mi = 0; mi < 2; ++mi)
                ldmatrix4(Abase + (m0 + mi * 16 + a_row) * ROWB + (k0 + a_kadd) * 2,
                          ra[mi][0], ra[mi][1], ra[mi][2], ra[mi][3]);
            uint32_t rb[4][4];
#pragma unroll
            for (int np = 0; np < 4; ++np)
                ldmatrix4(Bbase + (n0 + np * 16 + b_row) * ROWB + (k0 + b_kadd) * 2,
                          rb[np][0], rb[np][1], rb[np][2], rb[np][3]);
#pragma unroll
            for (int mi = 0; mi < 2; ++mi)
#pragma unroll
                for (int ni = 0; ni < 8; ++ni)
                    mma16816(acc[mi][ni], ra[mi],
                             rb[ni >> 1][(ni & 1) * 2 + 0], rb[ni >> 1][(ni & 1) * 2 + 1]);
        }
    }

    const int rbase = mbase + m0;
#pragma unroll
    for (int mi = 0; mi < 2; ++mi) {
#pragma unroll
        for (int ni = 0; ni < 8; ++ni) {
            int col = n0 + ni * 8 + (lane & 3) * 2;
            float b0 = g_biasproj[col], b1 = g_biasproj[col + 1];
            int r0 = rbase + mi * 16 + (lane >> 2);
            int r1 = r0 + 8;
            if (r0 < NSYM)
                *reinterpret_cast<float2*>(g_proj + (size_t)r0 * 256 + col) =
                    make_float2(acc[mi][ni][0] + b0, acc[mi][ni][1] + b1);
            if (r1 < NSYM)
                *reinterpret_cast<float2*>(g_proj + (size_t)r1 * 256 + col) =
                    make_float2(acc[mi][ni][2] + b0, acc[mi][ni][3] + b1);
        }
    }
}

// =====================================================================
// generic HMMA split GEMM: C[M,N] = (Ahi+Alo)[M,K] @ (Bhi+Blo)[N,K]^T
// options: +bias, +addMat, relu, fp32 out (nullable), bf16 hi/lo out.
// CTA tile 128x128, K-chunk 64, 256 threads (warps 4Mx2N of 32x64).
// =====================================================================
#define KROWB 144   // 128B data + 16B pad per 64-elem bf16 row
#define HG_AH 0
#define HG_AL (128 * KROWB)
#define HG_BH (2 * 128 * KROWB)
#define HG_BL (3 * 128 * KROWB)
#define HG_SMEM (4 * 128 * KROWB)   // 73728

__global__ void __launch_bounds__(256, 2)
hgemm_split(int M, int N, int K,
            const bf16* __restrict__ Ahi, const bf16* __restrict__ Alo,
            const bf16* __restrict__ Bhi, const bf16* __restrict__ Blo,
            const float* __restrict__ bias, const float* __restrict__ addMat,
            float* __restrict__ C, bf16* __restrict__ Chi, bf16* __restrict__ Clo,
            int doRelu) {
    extern __shared__ char sm[];
    const uint32_t sbase = smem_u32(sm);
    const int tid = threadIdx.x;
    const int mtile = blockIdx.y * 128, ntile = blockIdx.x * 128;

    const int warp = tid >> 5, lane = tid & 31;
    const int wm = warp & 3, wn = warp >> 2;
    const int m0 = wm * 32, n0 = wn * 64;

    float acc[2][8][4];
#pragma unroll
    for (int i = 0; i < 2; ++i)
#pragma unroll
        for (int j = 0; j < 8; ++j)
#pragma unroll
            for (int q = 0; q < 4; ++q) acc[i][j][q] = 0.f;

    const int a_row = (lane & 15);
    const int a_kadd = (lane >> 4) << 3;
    const int b_row = ((lane >> 4) << 3) + (lane & 7);
    const int b_kadd = ((lane >> 3) & 1) << 3;

    for (int kc = 0; kc < K; kc += 64) {
        // load A/B chunk (128 rows x 64 bf16, hi & lo): 1024 chunks each
#pragma unroll
        for (int i = 0; i < 4; ++i) {
            int c = tid + i * 256;
            int row = c >> 3, ch = c & 7;
            int gk = kc + ch * 8;
            int grow = mtile + row;
            uint4 h = make_uint4(0, 0, 0, 0), l = make_uint4(0, 0, 0, 0);
            if (grow < M) {
                h = *reinterpret_cast<const uint4*>(Ahi + (size_t)grow * K + gk);
                l = *reinterpret_cast<const uint4*>(Alo + (size_t)grow * K + gk);
            }
            int off = row * KROWB + ch * 16;
            *reinterpret_cast<uint4*>(sm + HG_AH + off) = h;
            *reinterpret_cast<uint4*>(sm + HG_AL + off) = l;
        }
#pragma unroll
        for (int i = 0; i < 4; ++i) {
            int c = tid + i * 256;
            int row = c >> 3, ch = c & 7;
            int gk = kc + ch * 8;
            int grow = ntile + row;  // N is a multiple of 128
            uint4 h = *reinterpret_cast<const uint4*>(Bhi + (size_t)grow * K + gk);
            uint4 l = *reinterpret_cast<const uint4*>(Blo + (size_t)grow * K + gk);
            int off = row * KROWB + ch * 16;
            *reinterpret_cast<uint4*>(sm + HG_BH + off) = h;
            *reinterpret_cast<uint4*>(sm + HG_BL + off) = l;
        }
        __syncthreads();

#pragma unroll
        for (int pass = 0; pass < 3; ++pass) {
            const uint32_t Abase = sbase + ((pass == 2) ? HG_AL : HG_AH);
            const uint32_t Bbase = sbase + ((pass == 1) ? HG_BL : HG_BH);
#pragma unroll
            for (int ks = 0; ks < 4; ++ks) {
                const int k0 = ks * 16;
                uint32_t ra[2][4];
#pragma unroll
                for (int mi = 0; mi < 2; ++mi)
                    ldmatrix4(Abase + (m0 + mi * 16 + a_row) * KROWB + (k0 + a_kadd) * 2,
                              ra[mi][0], ra[mi][1], ra[mi][2], ra[mi][3]);
                uint32_t rb[4][4];
#pragma unroll
                for (int np = 0; np < 4; ++np)
                    ldmatrix4(Bbase + (n0 + np * 16 + b_row) * KROWB + (k0 + b_kadd) * 2,
                              rb[np][0], rb[np][1], rb[np][2], rb[np][3]);
#pragma unroll
                for (int mi = 0; mi < 2; ++mi)
#pragma unroll
                    for (int ni = 0; ni < 8; ++ni)
                        mma16816(acc[mi][ni], ra[mi],
                                 rb[ni >> 1][(ni & 1) * 2 + 0], rb[ni >> 1][(ni & 1) * 2 + 1]);
            }
        }
        __syncthreads();
    }

    // epilogue
#pragma unroll
    for (int mi = 0; mi < 2; ++mi) {
#pragma unroll
        for (int ni = 0; ni < 8; ++ni) {
            int col = ntile + n0 + ni * 8 + (lane & 3) * 2;
            float b0 = bias ? bias[col] : 0.f;
            float b1 = bias ? bias[col + 1] : 0.f;
#pragma unroll
            for (int half = 0; half < 2; ++half) {
                int r = mtile + m0 + mi * 16 + (lane >> 2) + half * 8;
                if (r >= M) continue;
                float vx = acc[mi][ni][half * 2 + 0] + b0;
                float vy = acc[mi][ni][half * 2 + 1] + b1;
                if (addMat) {
                    vx += addMat[(size_t)r * N + col];
                    vy += addMat[(size_t)r * N + col + 1];
                }
                if (doRelu) { vx = fmaxf(vx, 0.f); vy = fmaxf(vy, 0.f); }
                if (C)
                    *reinterpret_cast<float2*>(C + (size_t)r * N + col) = make_float2(vx, vy);
                if (Chi) {
                    bf16 hx, lx, hy, ly;
                    split1(vx, hx, lx);
                    split1(vy, hy, ly);
                    *reinterpret_cast<uint32_t*>(Chi + (size_t)r * N + col) = pack_bf2(hx, hy);
                    *reinterpret_cast<uint32_t*>(Clo + (size_t)r * N + col) = pack_bf2(lx, ly);
                }
            }
        }
    }
}

// ---------------- neighbor encoder ----------------
__global__ void __launch_bounds__(128)
neighbor_kernel(const void* qlc, const void* qrc, const void* slc, const void* src) {
    __shared__ int sidx[2 * NB];
    int b = blockIdx.x;
    const void* conn;
    int node, off;
    if (b < BQ)                { conn = qlc; node = b;                off = node * DM; }
    else if (b < 2 * BQ)       { conn = qrc; node = b - BQ;           off = node * DM + 128; }
    else if (b < 2 * BQ + FEW) { conn = slc; node = b - 2 * BQ;       off = (BQ + node) * DM; }
    else                       { conn = src; node = b - 2 * BQ - FEW; off = (BQ + node) * DM + 128; }

    int tid = threadIdx.x;
    size_t base = (size_t)node * (2 * NB);
    if (g_is64) {
        const long long* p = (const long long*)conn;
        for (int t = tid; t < 2 * NB; t += 128) sidx[t] = (int)p[base + t];
    } else {
        const int* p = (const int*)conn;
        for (int t = tid; t < 2 * NB; t += 128) sidx[t] = p[base + t];
    }
    __syncthreads();

    const float* __restrict__ proj = g_proj;
    float m = -INFINITY;
#pragma unroll 2
    for (int k = 0; k < NB; ++k) {
        int rel = sidx[2 * k], ent = sidx[2 * k + 1];
        if (rel == PADID || ent == PADID) continue;
        float v = proj[rel * 256 + tid] + proj[ent * 256 + 128 + tid];
        v = (v > 0.f) ? v : 0.1f * v;
        m = fmaxf(m, v);
    }
    float t = tanhf(m);
    g_xcat[off + tid] = t;
    bf16 h, l;
    split1(t, h, l);
    g_xcathi[off + tid] = h;
    g_xcatlo[off + tid] = l;
}

// ---------------- layernorm + split ----------------
__global__ void ln_kernel(const float* __restrict__ lg, const float* __restrict__ lb) {
    __shared__ float red[256];
    int row = blockIdx.x, t = threadIdx.x;
    float v = g_oenc[row * DM + t];
    red[t] = v;
    __syncthreads();
    for (int s = 128; s > 0; s >>= 1) { if (t < s) red[t] += red[t + s]; __syncthreads(); }
    float mu = red[0] * (1.f / 256.f);
    __syncthreads();
    float d = v - mu;
    red[t] = d * d;
    __syncthreads();
    for (int s = 128; s > 0; s >>= 1) { if (t < s) red[t] += red[t + s]; __syncthreads(); }
    float var = red[0] * (1.f / 256.f);
    float o = d * rsqrtf(var + 1e-5f) * lg[t] + lb[t];
    g_enc[row * DM + t] = o;
    bf16 h, l;
    split1(o, h, l);
    g_enchi[row * DM + t] = h;
    g_enclo[row * DM + t] = l;
}

// ---------------- support_g mean ----------------
__global__ void mean_kernel() {
    int t = threadIdx.x;
    float s = 0.f;
    for (int r = 0; r < FEW; ++r) s += g_enc[(BQ + r) * DM + t];
    g_support[t] = s * (1.f / FEW);
}

// ---------------- sconst ----------------
__global__ void sconst_kernel(const float* __restrict__ Whh) {
    int gidx = (blockIdx.x * blockDim.x + threadIdx.x) >> 5;
    int lane = threadIdx.x & 31;
    if (gidx >= G4) return;
    float s = 0.f;
    for (int i = lane; i < DM; i += 32)
        s += g_support[i] * Whh[(size_t)gidx * 512 + 256 + i];
#pragma unroll
    for (int o = 16; o > 0; o >>= 1) s += __shfl_down_sync(0xffffffffu, s, o);
    if (lane == 0) g_sconst[gidx] = s;
}

// ---------------- LSTM elementwise step (+ h split) ----------------
__device__ __forceinline__ float sigm(float x) { return 1.f / (1.f + expf(-x)); }

__global__ void lstm_kernel(const float* __restrict__ G, int firstStep) {
    int idx = blockIdx.x * blockDim.x + threadIdx.x;
    if (idx >= BQ * HID) return;
    int n = idx >> 9, j = idx & 511;
    const float* g = G + (size_t)n * G4;
    float gi = g[j], gf = g[512 + j], gg = g[1024 + j], go = g[1536 + j];
    float c  = firstStep ? 0.f : g_c[idx];
    float cn = sigm(gf) * c + sigm(gi) * tanhf(gg);
    g_c[idx] = cn;
    if (j < DM) {
        float hv = g_enc[n * DM + j] + sigm(go) * tanhf(cn);
        g_h[n * DM + j] = hv;
        bf16 h, l;
        split1(hv, h, l);
        g_hhi[n * DM + j] = h;
        g_hlo[n * DM + j] = l;
    }
}

// ---------------- final dot ----------------
__global__ void final_kernel(float* __restrict__ out) {
    int n = (blockIdx.x * blockDim.x + threadIdx.x) >> 5;
    int lane = threadIdx.x & 31;
    if (n >= BQ) return;
    float s = 0.f;
    for (int i = lane; i < DM; i += 32)
        s += g_h[n * DM + i] * g_support[i];
#pragma unroll
    for (int o = 16; o > 0; o >>= 1) s += __shfl_down_sync(0xffffffffu, s, o);
    if (lane == 0) out[n] = s;
}

// ---------------- launch ----------------
extern "C" void kernel_launch(void* const* d_in, const int* in_sizes, int n_in,
                              void* d_out, int out_size) {
    const void* qlc = d_in[0];
    const void* qrc = d_in[1];
    const void* slc = d_in[2];
    const void* src = d_in[3];
    const float* emb  = (const float*)d_in[8];
    const float* gcnW = (const float*)d_in[9];
    const float* wb   = (const float*)d_in[10];
    const float* gb   = (const float*)d_in[11];
    const float* p1W  = (const float*)d_in[12];
    const float* p1b  = (const float*)d_in[13];
    const float* p2W  = (const float*)d_in[14];
    const float* p2b  = (const float*)d_in[15];
    const float* lng  = (const float*)d_in[16];
    const float* lnb  = (const float*)d_in[17];
    const float* Wih  = (const float*)d_in[18];
    const float* Whh  = (const float*)d_in[19];
    const float* bih  = (const float*)d_in[20];
    const float* bhh  = (const float*)d_in[21];

    // resolve device-global addresses
    bf16 *embhi, *emblo, *p1hi, *p1lo, *p2hi, *p2lo, *Wihhi, *Wihlo, *Whhhi, *Whhlo;
    bf16 *xcathi, *xcatlo, *henchi, *henclo, *enchi, *enclo, *hhi, *hlo;
    float *xcat, *oenc, *sconst, *qWihb, *gates, *bsum, *p1b_d = nullptr;
    cudaGetSymbolAddress((void**)&embhi, g_embhi);
    cudaGetSymbolAddress((void**)&emblo, g_emblo);
    cudaGetSymbolAddress((void**)&p1hi,  g_p1hi);
    cudaGetSymbolAddress((void**)&p1lo,  g_p1lo);
    cudaGetSymbolAddress((void**)&p2hi,  g_p2hi);
    cudaGetSymbolAddress((void**)&p2lo,  g_p2lo);
    cudaGetSymbolAddress((void**)&Wihhi, g_Wihhi);
    cudaGetSymbolAddress((void**)&Wihlo, g_Wihlo);
    cudaGetSymbolAddress((void**)&Whhhi, g_Whhhi);
    cudaGetSymbolAddress((void**)&Whhlo, g_Whhlo);
    cudaGetSymbolAddress((void**)&xcathi, g_xcathi);
    cudaGetSymbolAddress((void**)&xcatlo, g_xcatlo);
    cudaGetSymbolAddress((void**)&henchi, g_henchi);
    cudaGetSymbolAddress((void**)&henclo, g_henclo);
    cudaGetSymbolAddress((void**)&enchi,  g_enchi);
    cudaGetSymbolAddress((void**)&enclo,  g_enclo);
    cudaGetSymbolAddress((void**)&hhi,    g_hhi);
    cudaGetSymbolAddress((void**)&hlo,    g_hlo);
    cudaGetSymbolAddress((void**)&xcat,   g_xcat);
    cudaGetSymbolAddress((void**)&oenc,   g_oenc);
    cudaGetSymbolAddress((void**)&sconst, g_sconst);
    cudaGetSymbolAddress((void**)&qWihb,  g_qWihb);
    cudaGetSymbolAddress((void**)&gates,  g_gates);
    cudaGetSymbolAddress((void**)&bsum,   g_bsum);
    (void)p1b_d;

    detect_kernel<<<1, 1>>>((const int*)qlc);
    prep_kernel<<<128, 256>>>(gcnW, wb, gb, bih, bhh);

    // pre-split weights and embeddings
    split_w_kernel<<<(NSYM * 128 / 8 + 255) / 256, 256>>>(emb, NSYM * 128 / 8, 128, 128, embhi, emblo);
    split_w_kernel<<<(512 * 256 / 8 + 255) / 256, 256>>>(p1W, 512 * 256 / 8, 256, 256, p1hi, p1lo);
    split_w_kernel<<<(256 * 512 / 8 + 255) / 256, 256>>>(p2W, 256 * 512 / 8, 512, 512, p2hi, p2lo);
    split_w_kernel<<<(2048 * 256 / 8 + 255) / 256, 256>>>(Wih, 2048 * 256 / 8, 256, 256, Wihhi, Wihlo);
    split_w_kernel<<<(2048 * 256 / 8 + 255) / 256, 256>>>(Whh, 2048 * 256 / 8, 256, 512, Whhhi, Whhlo);

    // projected embedding table (HMMA)
    cudaFuncSetAttribute(proj_mma_kernel,
                         cudaFuncAttributeMaxDynamicSharedMemorySize, PROJ_SMEM);
    proj_mma_kernel<<<(NSYM + 127) / 128, 512, PROJ_SMEM>>>();

    // neighbor encoder (gather + max)
    neighbor_kernel<<<2 * BQ + 2 * FEW, 128>>>(qlc, qrc, slc, src);

    cudaFuncSetAttribute(hgemm_split,
                         cudaFuncAttributeMaxDynamicSharedMemorySize, HG_SMEM);

    // support encoder: henc = relu(xcat@p1W^T + p1b)  -> split only
    hgemm_split<<<dim3(512 / 128, (NROWS + 127) / 128), 256, HG_SMEM>>>(
        NROWS, 512, 256, xcathi, xcatlo, p1hi, p1lo, p1b, nullptr,
        nullptr, henchi, henclo, 1);
    // oenc = henc@p2W^T + p2b + xcat
    hgemm_split<<<dim3(256 / 128, (NROWS + 127) / 128), 256, HG_SMEM>>>(
        NROWS, 256, 512, henchi, henclo, p2hi, p2lo, p2b, xcat,
        oenc, nullptr, nullptr, 0);
    ln_kernel<<<NROWS, 256>>>(lng, lnb);

    mean_kernel<<<1, 256>>>();
    sconst_kernel<<<G4 * 32 / 256, 256>>>(Whh);

    // qWihb = enc@Wih^T + (b_ih + b_hh)
    hgemm_split<<<dim3(G4 / 128, BQ / 128), 256, HG_SMEM>>>(
        BQ, G4, 256, enchi, enclo, Wihhi, Wihlo, bsum, nullptr,
        qWihb, nullptr, nullptr, 0);

    lstm_kernel<<<(BQ * HID + 255) / 256, 256>>>(qWihb, 1);

    for (int s = 1; s < 4; ++s) {
        hgemm_split<<<dim3(G4 / 128, BQ / 128), 256, HG_SMEM>>>(
            BQ, G4, 256, hhi, hlo, Whhhi, Whhlo, sconst, qWihb,
            gates, nullptr, nullptr, 0);
        lstm_kernel<<<(BQ * HID + 255) / 256, 256>>>(gates, 0);
    }

    final_kernel<<<(BQ * 32 + 255) / 256, 256>>>((float*)d_out);
}